// round 14
// baseline (speedup 1.0000x reference)
#include <cuda_runtime.h>
#include <cstdint>
#include <math.h>

#define HH 128
#define NPIX 16384
#define PI_F 3.14159265358979f
#define NCLUST 296
#define BATCH 2048

// Batch-independent per-pixel angle table (filled by init kernel each launch).
__device__ float g_theta[NPIX];

__global__ void init_theta_kernel() {
    int idx = blockIdx.x * blockDim.x + threadIdx.x;
    if (idx < NPIX) {
        float fi = (float)(idx >> 7) - 64.0f;   // xx - cx
        float fj = (float)(idx & 127) - 64.0f;  // yy - cy
        g_theta[idx] = atan2f(fj, fi);
    }
}

__device__ __forceinline__ float fast_sqrt(float x) {
    float r;
    asm("sqrt.approx.f32 %0, %1;" : "=f"(r) : "f"(x));
    return r;
}

__device__ __forceinline__ void cp16(float* dst_smem, const float* src) {
    unsigned int a = (unsigned int)__cvta_generic_to_shared(dst_smem);
    asm volatile("cp.async.cg.shared.global [%0], [%1], 16;" :: "r"(a), "l"(src) : "memory");
}
#define CP_COMMIT() asm volatile("cp.async.commit_group;" ::: "memory")
#define CP_WAIT(n)  asm volatile("cp.async.wait_group %0;" :: "n"(n) : "memory")

#define CLUSTER_SYNC() do { \
    asm volatile("barrier.cluster.arrive.aligned;" ::: "memory"); \
    asm volatile("barrier.cluster.wait.aligned;" ::: "memory"); \
} while (0)

// Persistent 2-CTA clusters (R13 retry with fixed group discipline):
//  - theta refill for the next image = ONE commit group, cp16s spread through pass2
//  - FIFO ledger: pass1 entry sees {N0',N1',T'} (all old) -> k=0 wait(0);
//    k=1..6 wait(1); k=7 wait(1) if another image else wait(0).
// Per-thread byte ownership (thread t owns bytes 16t of every stage/block) keeps
// all cross-image prefetches barrier-free.
__global__ void __launch_bounds__(256, 4) __cluster_dims__(2, 1, 1) decode_kernel(
    const float* __restrict__ W,
    const float* __restrict__ ng,
    const float* __restrict__ nu,
    float* __restrict__ out)
{
    __shared__ float img_s[8192];           // 64 rows x 128 cols (theta landing + pixels)
    __shared__ float s_nbuf[2][2][1024];    // [stage buf][0=ng,1=nu]
    __shared__ float s_sinx[128];
    __shared__ float s_yacc[128];
    __shared__ float s_g1[128];
    __shared__ float s_mi[128];
    __shared__ float s_pr[128];
    __shared__ float s_sind[256];
    __shared__ float s_red[24];

    const int cid  = blockIdx.x >> 1;
    const int rank = blockIdx.x & 1;
    const int base = rank << 6;
    const int t = threadIdx.x;
    const int t4 = t << 2;
    const int j0 = (t & 31) * 4;
    const float dyf = (float)(j0 - 64);
    const int r0 = t >> 5;
    const int pg0 = ((base + r0) << 7) + j0;
    const float* thc = g_theta + (base << 7);
    const float SQRT10 = 3.16227766016838f;

    // ---- first-image prologue: groups N0, N1, T(single) -- mirrors steady state ----
    int b = cid;
    const float* ngc = ng + (size_t)b * NPIX + (base << 7);
    const float* nuc = nu + (size_t)b * NPIX + (base << 7);
    cp16(&s_nbuf[0][0][t4], ngc + t4);
    cp16(&s_nbuf[0][1][t4], nuc + t4);
    CP_COMMIT();                                   // N0
    cp16(&s_nbuf[1][0][t4], ngc + 1024 + t4);
    cp16(&s_nbuf[1][1][t4], nuc + 1024 + t4);
    CP_COMMIT();                                   // N1
#pragma unroll
    for (int p = 0; p < 8; ++p)
        cp16(&img_s[(p << 10) + t4], thc + (p << 10) + t4);
    CP_COMMIT();                                   // T (single group)

    for (;;) {
        // ---- per-image weights / params ----
        const float* Wb = W + b * 16;
        float w0  = __ldg(Wb + 0),  w1  = __ldg(Wb + 1),  w2  = __ldg(Wb + 2),  w3  = __ldg(Wb + 3);
        float w4  = __ldg(Wb + 4),  w5  = __ldg(Wb + 5),  w6  = __ldg(Wb + 6),  w7  = __ldg(Wb + 7);
        float w8  = __ldg(Wb + 8),  w9  = __ldg(Wb + 9),  w10 = __ldg(Wb + 10), w11 = __ldg(Wb + 11);
        float w12 = __ldg(Wb + 12), w13 = __ldg(Wb + 13), w14 = __ldg(Wb + 14), w15 = __ldg(Wb + 15);

        const float c0  = w0 * 6.0f;
        float hf = floorf(fminf(fmaxf(__fadd_rn(__fmul_rn(fabsf(w1), 8.0f), 2.0f), 2.0f), 12.0f));
        const int lo_ = 64 - (int)hf;
        const int hi_ = 64 + (int)hf;
        const float kx = w2 * (2.0f * PI_F / 128.0f);
        const float ky = w3 * (2.0f * PI_F / 128.0f);
        const float kd = w4 * (PI_F / 256.0f);
        const float a5 = w5 * 10.0f;
        const float off = truncf(w7 * 5.0f);
        const float bxf = 64.0f + off;                 // bx == by
        const float sigma = 4.0f + fabsf(w7) * 5.0f;
        const float ninv = -0.5f / (sigma * sigma);
        const float rw8 = w8 * 10.0f;
        const float cb = floorf(fminf(fmaxf(__fadd_rn(__fmul_rn(fabsf(w9), 8.0f), 2.0f), 2.0f), 16.0f));
        const float invcb = 1.0f / cb;
        const float angle = w10 * PI_F;
        float sa, ca;
        sincosf(angle, &sa, &ca);
        const float k11 = w11 * 4.0f;
        const float k12 = 0.2f * w12;
        const float k13 = 0.2f * w13;

        // ---- fill 1-D tables ----
        if (t < 128) {
            float tt = (float)t;
            s_sinx[t] = 0.5f * sinf(kx * tt);
            float db = tt - bxf;
            s_g1[t] = expf(db * db * ninv);
            int ip = (int)floorf((tt + 0.5f) * invcb);
            s_mi[t] = (ip & 1) ? 0.15f : -0.15f;        // -0.15 * p_i
            s_pr[t] = (ip & 1) ? -1.0f : 1.0f;          // p_j
            s_yacc[t] = 0.5f * sinf(ky * tt)
                      + 0.5f * sinf((tt + a5) * (PI_F / 128.0f))
                      + w6
                      - 0.5f * k13
                      + 0.15f;
        }
        s_sind[t] = 0.5f * sinf(kd * (float)t);
        __syncthreads();

        float yaccl[4], gyl[4], sqh[4], pjl[4];
#pragma unroll
        for (int l = 0; l < 4; ++l) {
            int jl = j0 + l;
            yaccl[l] = s_yacc[jl];
            gyl[l]  = s_g1[jl];
            pjl[l]  = s_pr[jl];
            sqh[l]  = (jl >= lo_ && jl < hi_) ? 0.5f : 0.0f;
        }

        float* op = out + (size_t)b * NPIX + pg0;
        const int bn = b + NCLUST;
        const bool hn = (bn < BATCH);
        const float* ngn = ng + (size_t)bn * NPIX + (base << 7);
        const float* nun = nu + (size_t)bn * NPIX + (base << 7);

        float mnv = __int_as_float(0x7f800000);
        float mxv = __int_as_float(0xff800000);

        // ---- pass 1 ----
#pragma unroll
        for (int k = 0; k < 8; ++k) {
            // FIFO ledger (steady state): entry {N0',N1',T'} all old -> k=0 drains them.
            if (k == 0)          CP_WAIT(0);
            else if (k < 7)      CP_WAIT(1);
            else { if (hn) CP_WAIT(1); else CP_WAIT(0); }

            const float4 g4 = *(const float4*)&s_nbuf[k & 1][0][t4];
            const float4 u4 = *(const float4*)&s_nbuf[k & 1][1][t4];
            const float4 tc = *(const float4*)&img_s[(k << 10) + t4];

            if (k < 6) {
                const int qn = (k + 2) << 10;
                cp16(&s_nbuf[k & 1][0][t4], ngc + qn + t4);
                cp16(&s_nbuf[k & 1][1][t4], nuc + qn + t4);
                CP_COMMIT();
            } else if (k == 6 && hn) {        // buf0 freed -> next image stage 0
                cp16(&s_nbuf[0][0][t4], ngn + t4);
                cp16(&s_nbuf[0][1][t4], nun + t4);
                CP_COMMIT();                  // N0'
            } else if (k == 7 && hn) {        // buf1 freed -> next image stage 1
                cp16(&s_nbuf[1][0][t4], ngn + 1024 + t4);
                cp16(&s_nbuf[1][1][t4], nun + 1024 + t4);
                CP_COMMIT();                  // N1'
            }

            const int i = base + r0 + (k << 3);
            const float dx = (float)i - 64.0f;
            const float dx2 = dx * dx;
            const float sinxi = s_sinx[i];
            const float g1i = s_g1[i];
            const float mi_i = s_mi[i];
            const float xm = (i >= lo_ && i < hi_) ? 1.0f : 0.0f;
            const float cadx = ca * dx;
            const int sb = i + j0;

            float gq[4] = {g4.x, g4.y, g4.z, g4.w};
            float uq[4] = {u4.x, u4.y, u4.z, u4.w};
            float thq[4] = {tc.x, tc.y, tc.z, tc.w};
            float v[4];
#pragma unroll
            for (int l = 0; l < 4; ++l) {
                const float dl = dyf + (float)l;
                float r = fast_sqrt(fmaf(dl, dl, dx2));
                float val = yaccl[l] + __saturatef(c0 - r);            // disk
                val = fmaf(xm, sqh[l], val);                           // central square
                val += sinxi;                                          // x-sinusoid
                val += s_sind[sb + l];                                 // diagonal sinusoid
                val = fmaf(g1i, gyl[l], val);                          // gaussian (separable)
                if (fabsf(r - rw8) < SQRT10) val += 1.0f;              // ring
                val = fmaf(mi_i, pjl[l], val);                         // checkerboard
                if (fabsf(fmaf(sa, dl, cadx)) < 3.0f) val += 0.6f;     // rotated line
                val = fmaf(0.5f, __sinf(thq[l] * k11), val);           // angular sinusoid
                val = fmaf(gq[l], k12, val);                           // gaussian noise
                val = fmaf(uq[l], k13, val);                           // uniform noise
                v[l] = val;
            }
            mnv = fminf(mnv, fminf(fminf(v[0], v[1]), fminf(v[2], v[3])));
            mxv = fmaxf(mxv, fmaxf(fmaxf(v[0], v[1]), fmaxf(v[2], v[3])));
            *(float4*)&img_s[(k << 10) + t4] = make_float4(v[0], v[1], v[2], v[3]);
        }

        // ---- local (half-image) min/max reduction ----
#pragma unroll
        for (int o = 16; o; o >>= 1) {
            mnv = fminf(mnv, __shfl_xor_sync(0xffffffffu, mnv, o));
            mxv = fmaxf(mxv, __shfl_xor_sync(0xffffffffu, mxv, o));
        }
        if ((t & 31) == 0) {
            s_red[t >> 5] = mnv;
            s_red[8 + (t >> 5)] = mxv;
        }
        __syncthreads();
        if (t == 0) {
            float gmn = s_red[0], gmx = s_red[8];
#pragma unroll
            for (int wdx = 1; wdx < 8; ++wdx) {
                gmn = fminf(gmn, s_red[wdx]);
                gmx = fmaxf(gmx, s_red[8 + wdx]);
            }
            s_red[16] = gmn;
            s_red[17] = gmx;
        }

        // ---- cluster exchange: combine halves ----
        CLUSTER_SYNC();
        if (t == 0) {
            unsigned int laddr = (unsigned int)__cvta_generic_to_shared(&s_red[16]);
            unsigned int paddr;
            unsigned int peer = (unsigned int)(rank ^ 1);
            asm("mapa.shared::cluster.u32 %0, %1, %2;" : "=r"(paddr) : "r"(laddr), "r"(peer));
            float pmn, pmx;
            asm("ld.shared::cluster.f32 %0, [%1];"   : "=f"(pmn) : "r"(paddr));
            asm("ld.shared::cluster.f32 %0, [%1+4];" : "=f"(pmx) : "r"(paddr));
            float gmn = fminf(s_red[16], pmn);
            float gmx = fmaxf(s_red[17], pmx);
            float c = 1.0f + w14;
            float pp = (w15 > 0.0f) ? -c : c;
            float ap = fabsf(pp);
            float denom = (gmx - gmn) + 1e-8f / ap;    // ap==0 -> inf -> A=0 -> out=0
            float A = ((pp > 0.0f) ? 1.0f : -1.0f) / denom;
            float x0 = (pp > 0.0f) ? gmn : gmx;
            s_red[18] = A;
            s_red[19] = x0;
        }
        CLUSTER_SYNC();

        const float A = s_red[18];
        const float C = -s_red[19] * A;

        // ---- pass 2: normalize + store; theta refill spread through, ONE commit ----
#pragma unroll
        for (int p = 0; p < 8; ++p) {
            const int q = p << 10;
            float4 vv = *(const float4*)&img_s[q + t4];
            vv.x = fmaf(vv.x, A, C);
            vv.y = fmaf(vv.y, A, C);
            vv.z = fmaf(vv.z, A, C);
            vv.w = fmaf(vv.w, A, C);
            *(float4*)(op + q) = vv;
            if (hn) cp16(&img_s[q + t4], thc + q + t4);   // same bytes just read
        }
        if (hn) CP_COMMIT();                              // T' (single group)

        if (!hn) break;
        b = bn;
        ngc = ngn;
        nuc = nun;
    }
}

extern "C" void kernel_launch(void* const* d_in, const int* in_sizes, int n_in,
                              void* d_out, int out_size) {
    const float* W  = (const float*)d_in[0];   // (2048, 16)
    const float* ng = (const float*)d_in[1];   // (2048, 128, 128)
    const float* nu = (const float*)d_in[2];   // (2048, 128, 128)
    float* out = (float*)d_out;                // (2048, 1, 128, 128)

    (void)in_sizes; (void)n_in; (void)out_size;

    init_theta_kernel<<<NPIX / 256, 256>>>();
    decode_kernel<<<2 * NCLUST, 256>>>(W, ng, nu, out);
}

// round 15
// speedup vs baseline: 1.7292x; 1.7292x over previous
#include <cuda_runtime.h>
#include <cstdint>
#include <math.h>

#define HH 128
#define NPIX 16384
#define PI_F 3.14159265358979f

// Batch-independent per-pixel angle table (filled by init kernel each launch).
__device__ float g_theta[NPIX];

__global__ void init_theta_kernel() {
    int idx = blockIdx.x * blockDim.x + threadIdx.x;
    if (idx < NPIX) {
        float fi = (float)(idx >> 7) - 64.0f;   // xx - cx
        float fj = (float)(idx & 127) - 64.0f;  // yy - cy
        g_theta[idx] = atan2f(fj, fi);
    }
}

__device__ __forceinline__ float fast_sqrt(float x) {
    float r;
    asm("sqrt.approx.f32 %0, %1;" : "=f"(r) : "f"(x));
    return r;
}

__device__ __forceinline__ void cp16(float* dst_smem, const float* src) {
    unsigned int a = (unsigned int)__cvta_generic_to_shared(dst_smem);
    asm volatile("cp.async.cg.shared.global [%0], [%1], 16;" :: "r"(a), "l"(src) : "memory");
}
#define CP_COMMIT() asm volatile("cp.async.commit_group;" ::: "memory")

#define CLUSTER_SYNC() do { \
    asm volatile("barrier.cluster.arrive.aligned;" ::: "memory"); \
    asm volatile("barrier.cluster.wait.aligned;" ::: "memory"); \
} while (0)

// R11 (best: 78.3us) + __stcs on the final output stores so the write-once out
// stream is marked evict-first in L2, protecting the hot theta table + noise
// streams that the cp.async pipeline depends on.
__global__ void __launch_bounds__(256, 4) __cluster_dims__(2, 1, 1) decode_kernel(
    const float* __restrict__ W,
    const float* __restrict__ ng,
    const float* __restrict__ nu,
    float* __restrict__ out)
{
    __shared__ float img_s[8192];           // 64 rows x 128 cols (doubles as theta landing)
    __shared__ float s_nbuf[2][2][1024];    // [stage buf][0=ng,1=nu][8 rows x 128]
    __shared__ float s_sinx[128];
    __shared__ float s_yacc[128];
    __shared__ float s_g1[128];
    __shared__ float s_mi[128];
    __shared__ float s_pr[128];
    __shared__ float s_sind[256];
    __shared__ float s_red[24];

    const int b    = blockIdx.x >> 1;
    const int rank = blockIdx.x & 1;
    const int base = rank << 6;          // first row of this CTA's half
    const int t = threadIdx.x;
    const int t4 = t << 2;               // this thread's float offset within a stage

    const size_t gbase = (size_t)b * NPIX;
    const float* ngc = ng + gbase + (base << 7);   // CTA-half base
    const float* nuc = nu + gbase + (base << 7);
    const float* thc = g_theta + (base << 7);

    // ---- prologue: start stages 0 and 1 of the pipeline immediately ----
    cp16(&s_nbuf[0][0][t4], ngc + t4);
    cp16(&s_nbuf[0][1][t4], nuc + t4);
    cp16(&img_s[t4],        thc + t4);          // theta stage 0 -> img block 0
    CP_COMMIT();
    cp16(&s_nbuf[1][0][t4], ngc + 1024 + t4);
    cp16(&s_nbuf[1][1][t4], nuc + 1024 + t4);
    cp16(&img_s[1024 + t4], thc + 1024 + t4);   // theta stage 1 -> img block 1
    CP_COMMIT();

    const float* Wb = W + b * 16;
    float w0  = __ldg(Wb + 0),  w1  = __ldg(Wb + 1),  w2  = __ldg(Wb + 2),  w3  = __ldg(Wb + 3);
    float w4  = __ldg(Wb + 4),  w5  = __ldg(Wb + 5),  w6  = __ldg(Wb + 6),  w7  = __ldg(Wb + 7);
    float w8  = __ldg(Wb + 8),  w9  = __ldg(Wb + 9),  w10 = __ldg(Wb + 10), w11 = __ldg(Wb + 11);
    float w12 = __ldg(Wb + 12), w13 = __ldg(Wb + 13), w14 = __ldg(Wb + 14), w15 = __ldg(Wb + 15);

    // ---- per-image params ----
    const float c0  = w0 * 6.0f;
    float hf = floorf(fminf(fmaxf(__fadd_rn(__fmul_rn(fabsf(w1), 8.0f), 2.0f), 2.0f), 12.0f));
    const int lo_ = 64 - (int)hf;
    const int hi_ = 64 + (int)hf;
    const float kx = w2 * (2.0f * PI_F / 128.0f);
    const float ky = w3 * (2.0f * PI_F / 128.0f);
    const float kd = w4 * (PI_F / 256.0f);
    const float a5 = w5 * 10.0f;
    const float off = truncf(w7 * 5.0f);
    const float bxf = 64.0f + off;                 // bx == by
    const float sigma = 4.0f + fabsf(w7) * 5.0f;
    const float ninv = -0.5f / (sigma * sigma);
    const float rw8 = w8 * 10.0f;
    const float cb = floorf(fminf(fmaxf(__fadd_rn(__fmul_rn(fabsf(w9), 8.0f), 2.0f), 2.0f), 16.0f));
    const float invcb = 1.0f / cb;
    const float angle = w10 * PI_F;
    float sa, ca;
    sincosf(angle, &sa, &ca);
    const float k11 = w11 * 4.0f;
    const float k12 = 0.2f * w12;
    const float k13 = 0.2f * w13;

    // ---- fill 1-D tables ----
    if (t < 128) {
        float tt = (float)t;
        s_sinx[t] = 0.5f * sinf(kx * tt);
        float db = tt - bxf;
        s_g1[t] = expf(db * db * ninv);
        int ip = (int)floorf((tt + 0.5f) * invcb);  // == floor(t/cb) for integer t, integer cb
        s_mi[t] = (ip & 1) ? 0.15f : -0.15f;        // -0.15 * p_i
        s_pr[t] = (ip & 1) ? -1.0f : 1.0f;          // p_j
        s_yacc[t] = 0.5f * sinf(ky * tt)
                  + 0.5f * sinf((tt + a5) * (PI_F / 128.0f))
                  + w6
                  - 0.5f * k13
                  + 0.15f;                           // checkerboard constant folded in
    }
    s_sind[t] = 0.5f * sinf(kd * (float)t);
    __syncthreads();

    // ---- per-thread j-quad constants ----
    const int j0 = (t & 31) * 4;
    const float dyf = (float)(j0 - 64);
    float yaccl[4], gyl[4], sqh[4], pjl[4];
#pragma unroll
    for (int l = 0; l < 4; ++l) {
        int jl = j0 + l;
        yaccl[l] = s_yacc[jl];
        gyl[l]  = s_g1[jl];
        pjl[l]  = s_pr[jl];
        sqh[l]  = (jl >= lo_ && jl < hi_) ? 0.5f : 0.0f;
    }

    const int r0 = t >> 5;                       // warp id = local row within 8-row group
    const int pg0 = ((base + r0) << 7) + j0;     // first global pixel for this thread
    float* op = out + gbase + pg0;

    const float SQRT10 = 3.16227766016838f;

    float mnv = __int_as_float(0x7f800000);
    float mxv = __int_as_float(0xff800000);

    // ---- pass 1: compute 64 rows into smem, fully cp.async-pipelined ----
#pragma unroll
    for (int k = 0; k < 8; ++k) {
        // wait for stage k (leave the newer in-flight group pending)
        if (k < 7) asm volatile("cp.async.wait_group 1;" ::: "memory");
        else       asm volatile("cp.async.wait_group 0;" ::: "memory");

        // consume my 16B of each stage buffer (theta lives in img block k)
        const float4 g4 = *(const float4*)&s_nbuf[k & 1][0][t4];
        const float4 u4 = *(const float4*)&s_nbuf[k & 1][1][t4];
        const float4 tc = *(const float4*)&img_s[(k << 10) + t4];

        // refill for stage k+2
        if (k < 6) {
            const int qn = (k + 2) << 10;
            cp16(&s_nbuf[k & 1][0][t4], ngc + qn + t4);
            cp16(&s_nbuf[k & 1][1][t4], nuc + qn + t4);
            cp16(&img_s[qn + t4],       thc + qn + t4);   // theta stage k+2 -> img block k+2
            CP_COMMIT();
        }

        const int i = base + r0 + (k << 3);      // global row
        const float dx = (float)i - 64.0f;
        const float dx2 = dx * dx;
        const float sinxi = s_sinx[i];
        const float g1i = s_g1[i];
        const float mi_i = s_mi[i];
        const float xm = (i >= lo_ && i < hi_) ? 1.0f : 0.0f;
        const float cadx = ca * dx;
        const int sb = i + j0;

        float gq[4] = {g4.x, g4.y, g4.z, g4.w};
        float uq[4] = {u4.x, u4.y, u4.z, u4.w};
        float thq[4] = {tc.x, tc.y, tc.z, tc.w};
        float v[4];
#pragma unroll
        for (int l = 0; l < 4; ++l) {
            const float dl = dyf + (float)l;
            float r = fast_sqrt(fmaf(dl, dl, dx2));
            float val = yaccl[l] + __saturatef(c0 - r);            // disk
            val = fmaf(xm, sqh[l], val);                           // central square
            val += sinxi;                                          // x-sinusoid
            val += s_sind[sb + l];                                 // diagonal sinusoid
            val = fmaf(g1i, gyl[l], val);                          // gaussian (separable)
            if (fabsf(r - rw8) < SQRT10) val += 1.0f;              // ring
            val = fmaf(mi_i, pjl[l], val);                         // checkerboard
            if (fabsf(fmaf(sa, dl, cadx)) < 3.0f) val += 0.6f;     // rotated line
            val = fmaf(0.5f, __sinf(thq[l] * k11), val);           // angular sinusoid
            val = fmaf(gq[l], k12, val);                           // gaussian noise
            val = fmaf(uq[l], k13, val);                           // uniform noise
            v[l] = val;
        }
        mnv = fminf(mnv, fminf(fminf(v[0], v[1]), fminf(v[2], v[3])));
        mxv = fmaxf(mxv, fmaxf(fmaxf(v[0], v[1]), fmaxf(v[2], v[3])));
        // overwrite this thread's own theta bytes with the computed pixels
        *(float4*)&img_s[(k << 10) + t4] = make_float4(v[0], v[1], v[2], v[3]);
    }

    // ---- local (half-image) min/max reduction ----
#pragma unroll
    for (int o = 16; o; o >>= 1) {
        mnv = fminf(mnv, __shfl_xor_sync(0xffffffffu, mnv, o));
        mxv = fmaxf(mxv, __shfl_xor_sync(0xffffffffu, mxv, o));
    }
    if ((t & 31) == 0) {
        s_red[t >> 5] = mnv;
        s_red[8 + (t >> 5)] = mxv;
    }
    __syncthreads();
    if (t == 0) {
        float gmn = s_red[0], gmx = s_red[8];
#pragma unroll
        for (int wdx = 1; wdx < 8; ++wdx) {
            gmn = fminf(gmn, s_red[wdx]);
            gmx = fmaxf(gmx, s_red[8 + wdx]);
        }
        s_red[16] = gmn;
        s_red[17] = gmx;
    }

    // ---- cluster exchange: combine halves ----
    CLUSTER_SYNC();   // release s_red[16..17] to peer; all cluster threads arrive
    if (t == 0) {
        unsigned int laddr = (unsigned int)__cvta_generic_to_shared(&s_red[16]);
        unsigned int paddr;
        unsigned int peer = (unsigned int)(rank ^ 1);
        asm("mapa.shared::cluster.u32 %0, %1, %2;" : "=r"(paddr) : "r"(laddr), "r"(peer));
        float pmn, pmx;
        asm("ld.shared::cluster.f32 %0, [%1];"   : "=f"(pmn) : "r"(paddr));
        asm("ld.shared::cluster.f32 %0, [%1+4];" : "=f"(pmx) : "r"(paddr));
        float gmn = fminf(s_red[16], pmn);
        float gmx = fmaxf(s_red[17], pmx);
        // fold contrast, inversion, min/max normalization into out = (x - x0) * A
        float c = 1.0f + w14;
        float pp = (w15 > 0.0f) ? -c : c;
        float ap = fabsf(pp);
        float denom = (gmx - gmn) + 1e-8f / ap;    // ap==0 -> inf -> A=0 -> out=0 (matches ref)
        float A = ((pp > 0.0f) ? 1.0f : -1.0f) / denom;
        float x0 = (pp > 0.0f) ? gmn : gmx;
        s_red[18] = A;
        s_red[19] = x0;
    }
    CLUSTER_SYNC();   // peer done reading our [16,17]; our threads see [18,19]

    const float A = s_red[18];
    const float C = -s_red[19] * A;

    // ---- pass 2: normalize from smem, streaming-store final (evict-first in L2) ----
#pragma unroll 4
    for (int k = 0; k < 8; ++k) {
        const int q = k << 10;
        float4 vv = *(const float4*)&img_s[q + t4];
        vv.x = fmaf(vv.x, A, C);
        vv.y = fmaf(vv.y, A, C);
        vv.z = fmaf(vv.z, A, C);
        vv.w = fmaf(vv.w, A, C);
        __stcs((float4*)(op + q), vv);
    }
}

extern "C" void kernel_launch(void* const* d_in, const int* in_sizes, int n_in,
                              void* d_out, int out_size) {
    const float* W  = (const float*)d_in[0];   // (2048, 16)
    const float* ng = (const float*)d_in[1];   // (2048, 128, 128)
    const float* nu = (const float*)d_in[2];   // (2048, 128, 128)
    float* out = (float*)d_out;                // (2048, 1, 128, 128)

    (void)in_sizes; (void)n_in; (void)out_size;

    init_theta_kernel<<<NPIX / 256, 256>>>();
    decode_kernel<<<4096, 256>>>(W, ng, nu, out);
}

// round 16
// speedup vs baseline: 1.7427x; 1.0078x over previous
#include <cuda_runtime.h>
#include <cstdint>
#include <math.h>

#define HH 128
#define NPIX 16384
#define PI_F 3.14159265358979f

// Batch-independent per-pixel angle table (filled by init kernel each launch).
__device__ float g_theta[NPIX];

__global__ void init_theta_kernel() {
    int idx = blockIdx.x * blockDim.x + threadIdx.x;
    if (idx < NPIX) {
        float fi = (float)(idx >> 7) - 64.0f;   // xx - cx
        float fj = (float)(idx & 127) - 64.0f;  // yy - cy
        g_theta[idx] = atan2f(fj, fi);
    }
}

__device__ __forceinline__ float fast_sqrt(float x) {
    float r;
    asm("sqrt.approx.f32 %0, %1;" : "=f"(r) : "f"(x));
    return r;
}

__device__ __forceinline__ void cp16(float* dst_smem, const float* src) {
    unsigned int a = (unsigned int)__cvta_generic_to_shared(dst_smem);
    asm volatile("cp.async.cg.shared.global [%0], [%1], 16;" :: "r"(a), "l"(src) : "memory");
}
#define CP_COMMIT() asm volatile("cp.async.commit_group;" ::: "memory")

#define CLUSTER_SYNC() do { \
    asm volatile("barrier.cluster.arrive.aligned;" ::: "memory"); \
    asm volatile("barrier.cluster.wait.aligned;" ::: "memory"); \
} while (0)

// R11/R15 structure (best) + fast-math table fill: the per-image 1-D tables that
// feed PURE ADDITIVE terms use __sinf/__expf (MUFU) instead of lib sinf/expf,
// cutting the serialized prologue before the table __syncthreads. All values
// feeding thresholds/predicates (hf, cb floors, rotated-line sa/ca) keep full
// precision.
__global__ void __launch_bounds__(256, 4) __cluster_dims__(2, 1, 1) decode_kernel(
    const float* __restrict__ W,
    const float* __restrict__ ng,
    const float* __restrict__ nu,
    float* __restrict__ out)
{
    __shared__ float img_s[8192];           // 64 rows x 128 cols (doubles as theta landing)
    __shared__ float s_nbuf[2][2][1024];    // [stage buf][0=ng,1=nu][8 rows x 128]
    __shared__ float s_sinx[128];
    __shared__ float s_yacc[128];
    __shared__ float s_g1[128];
    __shared__ float s_mi[128];
    __shared__ float s_pr[128];
    __shared__ float s_sind[256];
    __shared__ float s_red[24];

    const int b    = blockIdx.x >> 1;
    const int rank = blockIdx.x & 1;
    const int base = rank << 6;          // first row of this CTA's half
    const int t = threadIdx.x;
    const int t4 = t << 2;               // this thread's float offset within a stage

    const size_t gbase = (size_t)b * NPIX;
    const float* ngc = ng + gbase + (base << 7);   // CTA-half base
    const float* nuc = nu + gbase + (base << 7);
    const float* thc = g_theta + (base << 7);

    // ---- prologue: start stages 0 and 1 of the pipeline immediately ----
    cp16(&s_nbuf[0][0][t4], ngc + t4);
    cp16(&s_nbuf[0][1][t4], nuc + t4);
    cp16(&img_s[t4],        thc + t4);          // theta stage 0 -> img block 0
    CP_COMMIT();
    cp16(&s_nbuf[1][0][t4], ngc + 1024 + t4);
    cp16(&s_nbuf[1][1][t4], nuc + 1024 + t4);
    cp16(&img_s[1024 + t4], thc + 1024 + t4);   // theta stage 1 -> img block 1
    CP_COMMIT();

    const float* Wb = W + b * 16;
    float w0  = __ldg(Wb + 0),  w1  = __ldg(Wb + 1),  w2  = __ldg(Wb + 2),  w3  = __ldg(Wb + 3);
    float w4  = __ldg(Wb + 4),  w5  = __ldg(Wb + 5),  w6  = __ldg(Wb + 6),  w7  = __ldg(Wb + 7);
    float w8  = __ldg(Wb + 8),  w9  = __ldg(Wb + 9),  w10 = __ldg(Wb + 10), w11 = __ldg(Wb + 11);
    float w12 = __ldg(Wb + 12), w13 = __ldg(Wb + 13), w14 = __ldg(Wb + 14), w15 = __ldg(Wb + 15);

    // ---- per-image params ----
    const float c0  = w0 * 6.0f;
    float hf = floorf(fminf(fmaxf(__fadd_rn(__fmul_rn(fabsf(w1), 8.0f), 2.0f), 2.0f), 12.0f));
    const int lo_ = 64 - (int)hf;
    const int hi_ = 64 + (int)hf;
    const float kx = w2 * (2.0f * PI_F / 128.0f);
    const float ky = w3 * (2.0f * PI_F / 128.0f);
    const float kd = w4 * (PI_F / 256.0f);
    const float a5 = w5 * 10.0f;
    const float off = truncf(w7 * 5.0f);
    const float bxf = 64.0f + off;                 // bx == by
    const float sigma = 4.0f + fabsf(w7) * 5.0f;
    const float ninv = -0.5f / (sigma * sigma);
    const float rw8 = w8 * 10.0f;
    const float cb = floorf(fminf(fmaxf(__fadd_rn(__fmul_rn(fabsf(w9), 8.0f), 2.0f), 2.0f), 16.0f));
    const float invcb = 1.0f / cb;
    const float angle = w10 * PI_F;
    float sa, ca;
    sincosf(angle, &sa, &ca);        // lib precision: feeds |.|<3 boundary predicate
    const float k11 = w11 * 4.0f;
    const float k12 = 0.2f * w12;
    const float k13 = 0.2f * w13;

    // ---- fill 1-D tables (fast-math for additive-only tables) ----
    if (t < 128) {
        float tt = (float)t;
        s_sinx[t] = 0.5f * __sinf(kx * tt);
        float db = tt - bxf;
        s_g1[t] = __expf(db * db * ninv);
        int ip = (int)floorf((tt + 0.5f) * invcb);  // exact: integer parity semantics
        s_mi[t] = (ip & 1) ? 0.15f : -0.15f;        // -0.15 * p_i
        s_pr[t] = (ip & 1) ? -1.0f : 1.0f;          // p_j
        s_yacc[t] = 0.5f * __sinf(ky * tt)
                  + 0.5f * __sinf((tt + a5) * (PI_F / 128.0f))
                  + w6
                  - 0.5f * k13
                  + 0.15f;                           // checkerboard constant folded in
    }
    s_sind[t] = 0.5f * __sinf(kd * (float)t);
    __syncthreads();

    // ---- per-thread j-quad constants ----
    const int j0 = (t & 31) * 4;
    const float dyf = (float)(j0 - 64);
    float yaccl[4], gyl[4], sqh[4], pjl[4];
#pragma unroll
    for (int l = 0; l < 4; ++l) {
        int jl = j0 + l;
        yaccl[l] = s_yacc[jl];
        gyl[l]  = s_g1[jl];
        pjl[l]  = s_pr[jl];
        sqh[l]  = (jl >= lo_ && jl < hi_) ? 0.5f : 0.0f;
    }

    const int r0 = t >> 5;                       // warp id = local row within 8-row group
    const int pg0 = ((base + r0) << 7) + j0;     // first global pixel for this thread
    float* op = out + gbase + pg0;

    const float SQRT10 = 3.16227766016838f;

    float mnv = __int_as_float(0x7f800000);
    float mxv = __int_as_float(0xff800000);

    // ---- pass 1: compute 64 rows into smem, fully cp.async-pipelined ----
#pragma unroll
    for (int k = 0; k < 8; ++k) {
        // wait for stage k (leave the newer in-flight group pending)
        if (k < 7) asm volatile("cp.async.wait_group 1;" ::: "memory");
        else       asm volatile("cp.async.wait_group 0;" ::: "memory");

        // consume my 16B of each stage buffer (theta lives in img block k)
        const float4 g4 = *(const float4*)&s_nbuf[k & 1][0][t4];
        const float4 u4 = *(const float4*)&s_nbuf[k & 1][1][t4];
        const float4 tc = *(const float4*)&img_s[(k << 10) + t4];

        // refill for stage k+2
        if (k < 6) {
            const int qn = (k + 2) << 10;
            cp16(&s_nbuf[k & 1][0][t4], ngc + qn + t4);
            cp16(&s_nbuf[k & 1][1][t4], nuc + qn + t4);
            cp16(&img_s[qn + t4],       thc + qn + t4);   // theta stage k+2 -> img block k+2
            CP_COMMIT();
        }

        const int i = base + r0 + (k << 3);      // global row
        const float dx = (float)i - 64.0f;
        const float dx2 = dx * dx;
        const float sinxi = s_sinx[i];
        const float g1i = s_g1[i];
        const float mi_i = s_mi[i];
        const float xm = (i >= lo_ && i < hi_) ? 1.0f : 0.0f;
        const float cadx = ca * dx;
        const int sb = i + j0;

        float gq[4] = {g4.x, g4.y, g4.z, g4.w};
        float uq[4] = {u4.x, u4.y, u4.z, u4.w};
        float thq[4] = {tc.x, tc.y, tc.z, tc.w};
        float v[4];
#pragma unroll
        for (int l = 0; l < 4; ++l) {
            const float dl = dyf + (float)l;
            float r = fast_sqrt(fmaf(dl, dl, dx2));
            float val = yaccl[l] + __saturatef(c0 - r);            // disk
            val = fmaf(xm, sqh[l], val);                           // central square
            val += sinxi;                                          // x-sinusoid
            val += s_sind[sb + l];                                 // diagonal sinusoid
            val = fmaf(g1i, gyl[l], val);                          // gaussian (separable)
            if (fabsf(r - rw8) < SQRT10) val += 1.0f;              // ring
            val = fmaf(mi_i, pjl[l], val);                         // checkerboard
            if (fabsf(fmaf(sa, dl, cadx)) < 3.0f) val += 0.6f;     // rotated line
            val = fmaf(0.5f, __sinf(thq[l] * k11), val);           // angular sinusoid
            val = fmaf(gq[l], k12, val);                           // gaussian noise
            val = fmaf(uq[l], k13, val);                           // uniform noise
            v[l] = val;
        }
        mnv = fminf(mnv, fminf(fminf(v[0], v[1]), fminf(v[2], v[3])));
        mxv = fmaxf(mxv, fmaxf(fmaxf(v[0], v[1]), fmaxf(v[2], v[3])));
        // overwrite this thread's own theta bytes with the computed pixels
        *(float4*)&img_s[(k << 10) + t4] = make_float4(v[0], v[1], v[2], v[3]);
    }

    // ---- local (half-image) min/max reduction ----
#pragma unroll
    for (int o = 16; o; o >>= 1) {
        mnv = fminf(mnv, __shfl_xor_sync(0xffffffffu, mnv, o));
        mxv = fmaxf(mxv, __shfl_xor_sync(0xffffffffu, mxv, o));
    }
    if ((t & 31) == 0) {
        s_red[t >> 5] = mnv;
        s_red[8 + (t >> 5)] = mxv;
    }
    __syncthreads();
    if (t == 0) {
        float gmn = s_red[0], gmx = s_red[8];
#pragma unroll
        for (int wdx = 1; wdx < 8; ++wdx) {
            gmn = fminf(gmn, s_red[wdx]);
            gmx = fmaxf(gmx, s_red[8 + wdx]);
        }
        s_red[16] = gmn;
        s_red[17] = gmx;
    }

    // ---- cluster exchange: combine halves ----
    CLUSTER_SYNC();   // release s_red[16..17] to peer; all cluster threads arrive
    if (t == 0) {
        unsigned int laddr = (unsigned int)__cvta_generic_to_shared(&s_red[16]);
        unsigned int paddr;
        unsigned int peer = (unsigned int)(rank ^ 1);
        asm("mapa.shared::cluster.u32 %0, %1, %2;" : "=r"(paddr) : "r"(laddr), "r"(peer));
        float pmn, pmx;
        asm("ld.shared::cluster.f32 %0, [%1];"   : "=f"(pmn) : "r"(paddr));
        asm("ld.shared::cluster.f32 %0, [%1+4];" : "=f"(pmx) : "r"(paddr));
        float gmn = fminf(s_red[16], pmn);
        float gmx = fmaxf(s_red[17], pmx);
        // fold contrast, inversion, min/max normalization into out = (x - x0) * A
        float c = 1.0f + w14;
        float pp = (w15 > 0.0f) ? -c : c;
        float ap = fabsf(pp);
        float denom = (gmx - gmn) + 1e-8f / ap;    // ap==0 -> inf -> A=0 -> out=0 (matches ref)
        float A = ((pp > 0.0f) ? 1.0f : -1.0f) / denom;
        float x0 = (pp > 0.0f) ? gmn : gmx;
        s_red[18] = A;
        s_red[19] = x0;
    }
    CLUSTER_SYNC();   // peer done reading our [16,17]; our threads see [18,19]

    const float A = s_red[18];
    const float C = -s_red[19] * A;

    // ---- pass 2: normalize from smem, streaming-store final ----
#pragma unroll 4
    for (int k = 0; k < 8; ++k) {
        const int q = k << 10;
        float4 vv = *(const float4*)&img_s[q + t4];
        vv.x = fmaf(vv.x, A, C);
        vv.y = fmaf(vv.y, A, C);
        vv.z = fmaf(vv.z, A, C);
        vv.w = fmaf(vv.w, A, C);
        __stcs((float4*)(op + q), vv);
    }
}

extern "C" void kernel_launch(void* const* d_in, const int* in_sizes, int n_in,
                              void* d_out, int out_size) {
    const float* W  = (const float*)d_in[0];   // (2048, 16)
    const float* ng = (const float*)d_in[1];   // (2048, 128, 128)
    const float* nu = (const float*)d_in[2];   // (2048, 128, 128)
    float* out = (float*)d_out;                // (2048, 1, 128, 128)

    (void)in_sizes; (void)n_in; (void)out_size;

    init_theta_kernel<<<NPIX / 256, 256>>>();
    decode_kernel<<<4096, 256>>>(W, ng, nu, out);
}

// round 17
// speedup vs baseline: 1.7762x; 1.0192x over previous
#include <cuda_runtime.h>
#include <cstdint>
#include <math.h>

#define HH 128
#define NPIX 16384
#define PI_F 3.14159265358979f

// Batch-independent per-pixel angle table (filled by init kernel each launch).
__device__ float g_theta[NPIX];

__global__ void init_theta_kernel() {
    int idx = blockIdx.x * blockDim.x + threadIdx.x;
    if (idx < NPIX) {
        float fi = (float)(idx >> 7) - 64.0f;   // xx - cx
        float fj = (float)(idx & 127) - 64.0f;  // yy - cy
        g_theta[idx] = atan2f(fj, fi);
    }
}

__device__ __forceinline__ float fast_sqrt(float x) {
    float r;
    asm("sqrt.approx.f32 %0, %1;" : "=f"(r) : "f"(x));
    return r;
}

__device__ __forceinline__ void cp16(float* dst_smem, const float* src) {
    unsigned int a = (unsigned int)__cvta_generic_to_shared(dst_smem);
    asm volatile("cp.async.cg.shared.global [%0], [%1], 16;" :: "r"(a), "l"(src) : "memory");
}
#define CP_COMMIT() asm volatile("cp.async.commit_group;" ::: "memory")

// dynamic smem layout (floats)
#define SM_IMG   0            // 16384 (64KB image; doubles as theta landing)
#define SM_NB    16384        // s_nbuf[2][2][2048] = 8192
#define SM_SINX  24576        // 128
#define SM_YACC  24704        // 128
#define SM_G1    24832        // 128
#define SM_MI    24960        // 128
#define SM_PR    25088        // 128
#define SM_SIND  25216        // 256
#define SM_RED   25472        // 40
#define SM_TOTAL 25512
#define NB(st, strm) (SM_NB + (st) * 4096 + (strm) * 2048)

// One 512-thread CTA per image (R16 pipeline, cluster machinery removed):
// full image in dynamic smem, 16-row cp.async stages, block-level reduction.
// 2 CTAs/SM x 16 warps = same 32 warps/SM as the cluster version, minus the
// two ~380-cycle cluster barriers + DSMEM exchange per image.
__global__ void __launch_bounds__(512, 2) decode_kernel(
    const float* __restrict__ W,
    const float* __restrict__ ng,
    const float* __restrict__ nu,
    float* __restrict__ out)
{
    extern __shared__ float sm[];
    float* img_s = sm + SM_IMG;

    const int b = blockIdx.x;
    const int t = threadIdx.x;
    const int t4 = t << 2;               // this thread's float offset within a stage

    const size_t gbase = (size_t)b * NPIX;
    const float* ngc = ng + gbase;
    const float* nuc = nu + gbase;
    const float* thc = g_theta;

    // ---- prologue: start stages 0 and 1 of the pipeline immediately ----
    cp16(&sm[NB(0,0) + t4], ngc + t4);
    cp16(&sm[NB(0,1) + t4], nuc + t4);
    cp16(&img_s[t4],        thc + t4);          // theta stage 0 -> img block 0
    CP_COMMIT();
    cp16(&sm[NB(1,0) + t4], ngc + 2048 + t4);
    cp16(&sm[NB(1,1) + t4], nuc + 2048 + t4);
    cp16(&img_s[2048 + t4], thc + 2048 + t4);   // theta stage 1 -> img block 1
    CP_COMMIT();

    const float* Wb = W + b * 16;
    float w0  = __ldg(Wb + 0),  w1  = __ldg(Wb + 1),  w2  = __ldg(Wb + 2),  w3  = __ldg(Wb + 3);
    float w4  = __ldg(Wb + 4),  w5  = __ldg(Wb + 5),  w6  = __ldg(Wb + 6),  w7  = __ldg(Wb + 7);
    float w8  = __ldg(Wb + 8),  w9  = __ldg(Wb + 9),  w10 = __ldg(Wb + 10), w11 = __ldg(Wb + 11);
    float w12 = __ldg(Wb + 12), w13 = __ldg(Wb + 13), w14 = __ldg(Wb + 14), w15 = __ldg(Wb + 15);

    // ---- per-image params ----
    const float c0  = w0 * 6.0f;
    float hf = floorf(fminf(fmaxf(__fadd_rn(__fmul_rn(fabsf(w1), 8.0f), 2.0f), 2.0f), 12.0f));
    const int lo_ = 64 - (int)hf;
    const int hi_ = 64 + (int)hf;
    const float kx = w2 * (2.0f * PI_F / 128.0f);
    const float ky = w3 * (2.0f * PI_F / 128.0f);
    const float kd = w4 * (PI_F / 256.0f);
    const float a5 = w5 * 10.0f;
    const float off = truncf(w7 * 5.0f);
    const float bxf = 64.0f + off;                 // bx == by
    const float sigma = 4.0f + fabsf(w7) * 5.0f;
    const float ninv = -0.5f / (sigma * sigma);
    const float rw8 = w8 * 10.0f;
    const float cb = floorf(fminf(fmaxf(__fadd_rn(__fmul_rn(fabsf(w9), 8.0f), 2.0f), 2.0f), 16.0f));
    const float invcb = 1.0f / cb;
    const float angle = w10 * PI_F;
    float sa, ca;
    sincosf(angle, &sa, &ca);        // lib precision: feeds |.|<3 boundary predicate
    const float k11 = w11 * 4.0f;
    const float k12 = 0.2f * w12;
    const float k13 = 0.2f * w13;

    // ---- fill 1-D tables (fast-math for additive-only tables) ----
    if (t < 128) {
        float tt = (float)t;
        sm[SM_SINX + t] = 0.5f * __sinf(kx * tt);
        float db = tt - bxf;
        sm[SM_G1 + t] = __expf(db * db * ninv);
        int ip = (int)floorf((tt + 0.5f) * invcb);  // exact: integer parity semantics
        sm[SM_MI + t] = (ip & 1) ? 0.15f : -0.15f;  // -0.15 * p_i
        sm[SM_PR + t] = (ip & 1) ? -1.0f : 1.0f;    // p_j
        sm[SM_YACC + t] = 0.5f * __sinf(ky * tt)
                        + 0.5f * __sinf((tt + a5) * (PI_F / 128.0f))
                        + w6
                        - 0.5f * k13
                        + 0.15f;                     // checkerboard constant folded in
    }
    if (t < 256)
        sm[SM_SIND + t] = 0.5f * __sinf(kd * (float)t);
    __syncthreads();

    // ---- per-thread j-quad constants ----
    const int j0 = (t & 31) * 4;
    const float dyf = (float)(j0 - 64);
    float yaccl[4], gyl[4], sqh[4], pjl[4];
#pragma unroll
    for (int l = 0; l < 4; ++l) {
        int jl = j0 + l;
        yaccl[l] = sm[SM_YACC + jl];
        gyl[l]  = sm[SM_G1 + jl];
        pjl[l]  = sm[SM_PR + jl];
        sqh[l]  = (jl >= lo_ && jl < hi_) ? 0.5f : 0.0f;
    }

    const int r0 = t >> 5;                       // warp id = row within 16-row group
    float* op = out + gbase + t4;                // t4 == r0*128 + j0

    const float SQRT10 = 3.16227766016838f;

    float mnv = __int_as_float(0x7f800000);
    float mxv = __int_as_float(0xff800000);

    // ---- pass 1: compute 128 rows into smem, fully cp.async-pipelined ----
#pragma unroll
    for (int k = 0; k < 8; ++k) {
        // wait for stage k (leave the newer in-flight group pending)
        if (k < 7) asm volatile("cp.async.wait_group 1;" ::: "memory");
        else       asm volatile("cp.async.wait_group 0;" ::: "memory");

        const int q = k << 11;                   // k * 16 rows * 128
        const float4 g4 = *(const float4*)&sm[NB(k & 1, 0) + t4];
        const float4 u4 = *(const float4*)&sm[NB(k & 1, 1) + t4];
        const float4 tc = *(const float4*)&img_s[q + t4];

        // refill for stage k+2
        if (k < 6) {
            const int qn = (k + 2) << 11;
            cp16(&sm[NB(k & 1, 0) + t4], ngc + qn + t4);
            cp16(&sm[NB(k & 1, 1) + t4], nuc + qn + t4);
            cp16(&img_s[qn + t4],        thc + qn + t4);   // theta stage k+2
            CP_COMMIT();
        }

        const int i = r0 + (k << 4);             // global row
        const float dx = (float)i - 64.0f;
        const float dx2 = dx * dx;
        const float sinxi = sm[SM_SINX + i];
        const float g1i = sm[SM_G1 + i];
        const float mi_i = sm[SM_MI + i];
        const float xm = (i >= lo_ && i < hi_) ? 1.0f : 0.0f;
        const float cadx = ca * dx;
        const int sb = SM_SIND + i + j0;

        float gq[4] = {g4.x, g4.y, g4.z, g4.w};
        float uq[4] = {u4.x, u4.y, u4.z, u4.w};
        float thq[4] = {tc.x, tc.y, tc.z, tc.w};
        float v[4];
#pragma unroll
        for (int l = 0; l < 4; ++l) {
            const float dl = dyf + (float)l;
            float r = fast_sqrt(fmaf(dl, dl, dx2));
            float val = yaccl[l] + __saturatef(c0 - r);            // disk
            val = fmaf(xm, sqh[l], val);                           // central square
            val += sinxi;                                          // x-sinusoid
            val += sm[sb + l];                                     // diagonal sinusoid
            val = fmaf(g1i, gyl[l], val);                          // gaussian (separable)
            if (fabsf(r - rw8) < SQRT10) val += 1.0f;              // ring
            val = fmaf(mi_i, pjl[l], val);                         // checkerboard
            if (fabsf(fmaf(sa, dl, cadx)) < 3.0f) val += 0.6f;     // rotated line
            val = fmaf(0.5f, __sinf(thq[l] * k11), val);           // angular sinusoid
            val = fmaf(gq[l], k12, val);                           // gaussian noise
            val = fmaf(uq[l], k13, val);                           // uniform noise
            v[l] = val;
        }
        mnv = fminf(mnv, fminf(fminf(v[0], v[1]), fminf(v[2], v[3])));
        mxv = fmaxf(mxv, fmaxf(fmaxf(v[0], v[1]), fmaxf(v[2], v[3])));
        // overwrite this thread's own theta bytes with the computed pixels
        *(float4*)&img_s[q + t4] = make_float4(v[0], v[1], v[2], v[3]);
    }

    // ---- block min/max reduction (16 warps) ----
#pragma unroll
    for (int o = 16; o; o >>= 1) {
        mnv = fminf(mnv, __shfl_xor_sync(0xffffffffu, mnv, o));
        mxv = fmaxf(mxv, __shfl_xor_sync(0xffffffffu, mxv, o));
    }
    if ((t & 31) == 0) {
        sm[SM_RED + (t >> 5)] = mnv;
        sm[SM_RED + 16 + (t >> 5)] = mxv;
    }
    __syncthreads();
    if (t == 0) {
        float gmn = sm[SM_RED + 0], gmx = sm[SM_RED + 16];
#pragma unroll
        for (int wdx = 1; wdx < 16; ++wdx) {
            gmn = fminf(gmn, sm[SM_RED + wdx]);
            gmx = fmaxf(gmx, sm[SM_RED + 16 + wdx]);
        }
        // fold contrast, inversion, min/max normalization into out = (x - x0) * A
        float c = 1.0f + w14;
        float pp = (w15 > 0.0f) ? -c : c;
        float ap = fabsf(pp);
        float denom = (gmx - gmn) + 1e-8f / ap;    // ap==0 -> inf -> A=0 -> out=0 (matches ref)
        float A = ((pp > 0.0f) ? 1.0f : -1.0f) / denom;
        float x0 = (pp > 0.0f) ? gmn : gmx;
        sm[SM_RED + 32] = A;
        sm[SM_RED + 33] = x0;
    }
    __syncthreads();

    const float A = sm[SM_RED + 32];
    const float C = -sm[SM_RED + 33] * A;

    // ---- pass 2: normalize from smem, streaming-store final ----
#pragma unroll 4
    for (int k = 0; k < 8; ++k) {
        const int q = k << 11;
        float4 vv = *(const float4*)&img_s[q + t4];
        vv.x = fmaf(vv.x, A, C);
        vv.y = fmaf(vv.y, A, C);
        vv.z = fmaf(vv.z, A, C);
        vv.w = fmaf(vv.w, A, C);
        __stcs((float4*)(op + q), vv);
    }
}

extern "C" void kernel_launch(void* const* d_in, const int* in_sizes, int n_in,
                              void* d_out, int out_size) {
    const float* W  = (const float*)d_in[0];   // (2048, 16)
    const float* ng = (const float*)d_in[1];   // (2048, 128, 128)
    const float* nu = (const float*)d_in[2];   // (2048, 128, 128)
    float* out = (float*)d_out;                // (2048, 1, 128, 128)

    (void)in_sizes; (void)n_in; (void)out_size;

    const int smem_bytes = SM_TOTAL * sizeof(float);
    cudaFuncSetAttribute(decode_kernel, cudaFuncAttributeMaxDynamicSharedMemorySize, smem_bytes);

    init_theta_kernel<<<NPIX / 256, 256>>>();
    decode_kernel<<<2048, 512, smem_bytes>>>(W, ng, nu, out);
}